// round 7
// baseline (speedup 1.0000x reference)
#include <cuda_runtime.h>
#include <cuda_fp16.h>
#include <cstdint>

#define N_NODES 50000
#define F1 64
#define F2 128
#define F3 64
#define MAX_E 800000

// ---------------- device scratch ----------------
__device__ int     g_cnt  [N_NODES];             // in-degree (excl. self-loop)
__device__ int2    g_ed   [MAX_E];               // packed {src, dst}
__device__ __half  g_zsh  [N_NODES * F1];        // (z * dinv) fp16 (gather src L1)
__device__ __half  g_agg1h[2 * N_NODES * F1];    // 2-way split fp16 accum L1
__device__ float   g_x    [N_NODES * F2];        // relu(layer1)
__device__ __half  g_h2h  [N_NODES * F3];        // (h2 * dinv) fp16 (gather src L2)
__device__ __half  g_agg2h[2 * N_NODES * F3];    // 2-way split fp16 accum L2
__device__ int     g_is64;

__device__ __forceinline__ void red4h(__half* p, uint32_t a, uint32_t b,
                                      uint32_t c, uint32_t d) {
    asm volatile("red.global.add.noftz.v4.f16x2 [%0], {%1,%2,%3,%4};"
                 :: "l"(p), "r"(a), "r"(b), "r"(c), "r"(d) : "memory");
}

__device__ __forceinline__ float rinv_of(int m) {
    return rsqrtf((float)(g_cnt[m] + 1));
}

// ---------------- init: zero histogram + dtype detect ----------------
__global__ void init_kernel(const long long* ei, int M) {
    int i = blockIdx.x * 256 + threadIdx.x;
    if (i < M) g_cnt[i] = 0;
    if (blockIdx.x == 0 && threadIdx.x == 0) {
        bool ok = true;
#pragma unroll
        for (int k = 0; k < 8; k++) {
            long long v = ei[k];
            if (v < 0 || v >= N_NODES) ok = false;
        }
        g_is64 = ok ? 1 : 0;   // int32 data read as int64 lands out of range
    }
}

// ---------------- pack edges to int2 + degree histogram ----------------
__global__ void pack_deg_kernel(const void* ei, int nE) {
    int e = blockIdx.x * 256 + threadIdx.x;
    if (e >= nE) return;
    int s, d;
    if (g_is64) {
        s = (int)((const long long*)ei)[e];
        d = (int)((const long long*)ei)[(long long)nE + e];
    } else {
        s = ((const int*)ei)[e];
        d = ((const int*)ei)[nE + e];
    }
    g_ed[e] = make_int2(s, d);
    atomicAdd(&g_cnt[d], 1);
}

// ---- scale1: zsh = half(z*dinv); agg1 buf0 seeded with self, buf1 zeroed ----
__global__ __launch_bounds__(256) void scale1_kernel(const float4* __restrict__ z4, int M) {
    int i = blockIdx.x * 256 + threadIdx.x;     // over M*16 float4
    if (i >= M * 16) return;
    float r = rinv_of(i >> 4);
    float4 v = z4[i];
    __half2 h0 = __floats2half2_rn(v.x * r, v.y * r);
    __half2 h1 = __floats2half2_rn(v.z * r, v.w * r);
    __half2 zz = __floats2half2_rn(0.f, 0.f);
    ((__half2*)g_zsh)[i * 2 + 0] = h0;
    ((__half2*)g_zsh)[i * 2 + 1] = h1;
    ((__half2*)g_agg1h)[i * 2 + 0] = h0;                    // buf0 = self seed
    ((__half2*)g_agg1h)[i * 2 + 1] = h1;
    ((__half2*)(g_agg1h + N_NODES * F1))[i * 2 + 0] = zz;   // buf1 = 0
    ((__half2*)(g_agg1h + N_NODES * F1))[i * 2 + 1] = zz;
}

// ---- agg: 8 threads/edge, 16B fp16 gather, one red.v4.f16x2, parity-split dst ----
__device__ __forceinline__ void agg_body(const __half* __restrict__ src,
                                         __half* __restrict__ dst, int nE, int stride) {
    int t = blockIdx.x * 256 + threadIdx.x;
    int e = t >> 3;
    if (e >= nE) return;
    int j = t & 7;
    int2 ed = g_ed[e];
    uint4 v = ((const uint4*)src)[ed.x * 8 + j];            // 8 halves
    red4h(dst + (e & 1) * stride + ed.y * 64 + j * 8, v.x, v.y, v.z, v.w);
}

__global__ __launch_bounds__(256) void agg1_kernel(int nE) {
    agg_body(g_zsh, g_agg1h, nE, N_NODES * F1);
}

__global__ __launch_bounds__(256) void agg2_kernel(int nE) {
    agg_body(g_h2h, g_agg2h, nE, N_NODES * F3);
}

// ------- GEMM1: x = relu( ((buf0+buf1)*dinv) @ W1 + b1 )  [M,64]x[64,128] -------
__global__ __launch_bounds__(256) void gemm1_kernel(const float* __restrict__ W1,
                                                    const float* __restrict__ b1,
                                                    int M) {
    __shared__ float Ws[F1 * F2];         // 32 KB
    __shared__ float As[64 * F1];         // 16 KB
    int tid = threadIdx.x;
    int m0  = blockIdx.x * 64;

    const float4* W14 = (const float4*)W1;
    float4* Ws4 = (float4*)Ws;
#pragma unroll
    for (int i = 0; i < 8; i++) Ws4[tid + 256 * i] = W14[tid + 256 * i];

    const uint4* ag0 = (const uint4*)g_agg1h;
    const uint4* ag1 = (const uint4*)(g_agg1h + N_NODES * F1);
#pragma unroll
    for (int i = 0; i < 2; i++) {
        int t   = tid + 256 * i;          // 0..511
        int row = m0 + (t >> 3);
        int c   = t & 7;
        float4 lo = make_float4(0.f, 0.f, 0.f, 0.f), hi = lo;
        if (row < M) {
            uint4 v0 = ag0[row * 8 + c];
            uint4 v1 = ag1[row * 8 + c];
            float r = rinv_of(row);
            float2 a0 = __half22float2(*(const __half2*)&v0.x);
            float2 a1 = __half22float2(*(const __half2*)&v0.y);
            float2 a2 = __half22float2(*(const __half2*)&v0.z);
            float2 a3 = __half22float2(*(const __half2*)&v0.w);
            float2 c0 = __half22float2(*(const __half2*)&v1.x);
            float2 c1 = __half22float2(*(const __half2*)&v1.y);
            float2 c2 = __half22float2(*(const __half2*)&v1.z);
            float2 c3 = __half22float2(*(const __half2*)&v1.w);
            lo = make_float4((a0.x + c0.x) * r, (a0.y + c0.y) * r,
                             (a1.x + c1.x) * r, (a1.y + c1.y) * r);
            hi = make_float4((a2.x + c2.x) * r, (a2.y + c2.y) * r,
                             (a3.x + c3.x) * r, (a3.y + c3.y) * r);
        }
        int base = (t >> 3) * F1 + c * 8;
        *(float4*)&As[base]     = lo;
        *(float4*)&As[base + 4] = hi;
    }
    __syncthreads();

    int tx = tid & 31, ty = tid >> 5;
    int c = tx * 4, r0 = ty * 8;
    float acc[8][4];
#pragma unroll
    for (int i = 0; i < 8; i++)
#pragma unroll
        for (int jj = 0; jj < 4; jj++) acc[i][jj] = 0.f;

#pragma unroll
    for (int k = 0; k < F1; k++) {
        float4 wv = *(const float4*)&Ws[k * F2 + c];
#pragma unroll
        for (int i = 0; i < 8; i++) {
            float a = As[(r0 + i) * F1 + k];
            acc[i][0] += a * wv.x;
            acc[i][1] += a * wv.y;
            acc[i][2] += a * wv.z;
            acc[i][3] += a * wv.w;
        }
    }

    float4 bb = *(const float4*)&b1[c];
#pragma unroll
    for (int i = 0; i < 8; i++) {
        int m = m0 + r0 + i;
        if (m < M) {
            float4 o;
            o.x = fmaxf(acc[i][0] + bb.x, 0.f);
            o.y = fmaxf(acc[i][1] + bb.y, 0.f);
            o.z = fmaxf(acc[i][2] + bb.z, 0.f);
            o.w = fmaxf(acc[i][3] + bb.w, 0.f);
            ((float4*)g_x)[m * 32 + tx] = o;
        }
    }
}

// ---- GEMM2 (+fused scale2): h2h = buf0_seed = half((x@W2)*dinv), buf1 = 0 ----
__global__ __launch_bounds__(256) void gemm2_kernel(const float* __restrict__ W2, int M) {
    __shared__ float  Ws[F2 * F3];        // 32 KB
    __shared__ float4 As4[64 * 8];        // 8 KB
    int tid = threadIdx.x;
    int m0  = blockIdx.x * 64;

    const float4* W24 = (const float4*)W2;
    float4* Ws4 = (float4*)Ws;
#pragma unroll
    for (int i = 0; i < 8; i++) Ws4[tid + 256 * i] = W24[tid + 256 * i];

    int tx = tid & 15, ty = tid >> 4;
    float acc[4][4];
#pragma unroll
    for (int i = 0; i < 4; i++)
#pragma unroll
        for (int jj = 0; jj < 4; jj++) acc[i][jj] = 0.f;

    const float* As = (const float*)As4;
    const float4* x4 = (const float4*)g_x;

    for (int kc = 0; kc < 4; kc++) {
        __syncthreads();
#pragma unroll
        for (int i = 0; i < 2; i++) {
            int t   = tid + 256 * i;
            int row = m0 + (t >> 3);
            int c4  = t & 7;
            As4[t] = (row < M) ? x4[row * 32 + kc * 8 + c4]
                               : make_float4(0.f, 0.f, 0.f, 0.f);
        }
        __syncthreads();
#pragma unroll
        for (int kk = 0; kk < 32; kk++) {
            int k = kc * 32 + kk;
            float4 wv = *(const float4*)&Ws[k * F3 + tx * 4];
#pragma unroll
            for (int i = 0; i < 4; i++) {
                float a = As[(ty * 4 + i) * 32 + kk];
                acc[i][0] += a * wv.x;
                acc[i][1] += a * wv.y;
                acc[i][2] += a * wv.z;
                acc[i][3] += a * wv.w;
            }
        }
    }

#pragma unroll
    for (int i = 0; i < 4; i++) {
        int m = m0 + ty * 4 + i;
        if (m < M) {
            float r = rinv_of(m);
            __half2 h0 = __floats2half2_rn(acc[i][0] * r, acc[i][1] * r);
            __half2 h1 = __floats2half2_rn(acc[i][2] * r, acc[i][3] * r);
            __half2 zz = __floats2half2_rn(0.f, 0.f);
            int b = m * 32 + tx * 2;
            ((__half2*)g_h2h)[b]     = h0;
            ((__half2*)g_h2h)[b + 1] = h1;
            ((__half2*)g_agg2h)[b]     = h0;                    // buf0 = self seed
            ((__half2*)g_agg2h)[b + 1] = h1;
            ((__half2*)(g_agg2h + N_NODES * F3))[b]     = zz;   // buf1 = 0
            ((__half2*)(g_agg2h + N_NODES * F3))[b + 1] = zz;
        }
    }
}

// ------- epilogue: out = relu((buf0+buf1)*dinv + b2) -------
__global__ __launch_bounds__(256) void epilogue_kernel(const float* __restrict__ b2,
                                                       float* __restrict__ out, int M) {
    int i = blockIdx.x * 256 + threadIdx.x;     // over M*8 uint4-of-halves
    if (i >= M * 8) return;
    int m = i >> 3, c = i & 7;
    float r = rinv_of(m);
    uint4 v0 = ((const uint4*)g_agg2h)[i];
    uint4 v1 = ((const uint4*)(g_agg2h + N_NODES * F3))[i];
    float2 a0 = __half22float2(*(const __half2*)&v0.x);
    float2 a1 = __half22float2(*(const __half2*)&v0.y);
    float2 a2 = __half22float2(*(const __half2*)&v0.z);
    float2 a3 = __half22float2(*(const __half2*)&v0.w);
    float2 c0 = __half22float2(*(const __half2*)&v1.x);
    float2 c1 = __half22float2(*(const __half2*)&v1.y);
    float2 c2 = __half22float2(*(const __half2*)&v1.z);
    float2 c3 = __half22float2(*(const __half2*)&v1.w);
    float4 blo = *(const float4*)(b2 + c * 8);
    float4 bhi = *(const float4*)(b2 + c * 8 + 4);
    float4 o0, o1;
    o0.x = fmaxf((a0.x + c0.x) * r + blo.x, 0.f);
    o0.y = fmaxf((a0.y + c0.y) * r + blo.y, 0.f);
    o0.z = fmaxf((a1.x + c1.x) * r + blo.z, 0.f);
    o0.w = fmaxf((a1.y + c1.y) * r + blo.w, 0.f);
    o1.x = fmaxf((a2.x + c2.x) * r + bhi.x, 0.f);
    o1.y = fmaxf((a2.y + c2.y) * r + bhi.y, 0.f);
    o1.z = fmaxf((a3.x + c3.x) * r + bhi.z, 0.f);
    o1.w = fmaxf((a3.y + c3.y) * r + bhi.w, 0.f);
    ((float4*)out)[i * 2 + 0] = o0;
    ((float4*)out)[i * 2 + 1] = o1;
}

// ---------------- launch ----------------
extern "C" void kernel_launch(void* const* d_in, const int* in_sizes, int n_in,
                              void* d_out, int out_size) {
    const float* z  = (const float*)d_in[0];
    const void*  ei = d_in[1];
    const float* W1 = (const float*)d_in[2];
    const float* b1 = (const float*)d_in[3];
    const float* W2 = (const float*)d_in[4];
    const float* b2 = (const float*)d_in[5];
    float* out = (float*)d_out;

    int nE = in_sizes[1] / 2;
    int M  = in_sizes[0] / F1;

    int nb_nodes = (M + 255) / 256;
    int nb_edge  = (nE + 255) / 256;
    int nb_agg   = (nE * 8 + 255) / 256;
    int nb_vec   = (M * 16 + 255) / 256;
    int nb_epi   = (M * 8 + 255) / 256;
    int nb_gemm  = (M + 63) / 64;

    init_kernel<<<nb_nodes, 256>>>((const long long*)ei, M);
    pack_deg_kernel<<<nb_edge, 256>>>(ei, nE);
    scale1_kernel<<<nb_vec, 256>>>((const float4*)z, M);
    agg1_kernel<<<nb_agg, 256>>>(nE);
    gemm1_kernel<<<nb_gemm, 256>>>(W1, b1, M);
    gemm2_kernel<<<nb_gemm, 256>>>(W2, M);
    agg2_kernel<<<nb_agg, 256>>>(nE);
    epilogue_kernel<<<nb_epi, 256>>>(b2, out, M);
}

// round 8
// speedup vs baseline: 1.2115x; 1.2115x over previous
#include <cuda_runtime.h>
#include <cuda_fp16.h>
#include <cstdint>

#define N_NODES 50000
#define F1 64
#define F2 128
#define F3 64
#define MAX_E 800000

// ---------------- device scratch ----------------
__device__ int     g_cnt  [N_NODES];             // in-degree (excl. self-loop)
__device__ int2    g_ed   [MAX_E];               // packed {src, dst}
__device__ __half  g_zsh  [N_NODES * F1];        // (z * dinv) fp16 (gather src L1)
__device__ __half  g_agg1h[2 * N_NODES * F1];    // 2-way split fp16 accum L1
__device__ __half  g_xh   [N_NODES * F2];        // relu(layer1) fp16
__device__ __half  g_h2h  [N_NODES * F3];        // (h2 * dinv) fp16 (gather src L2)
__device__ __half  g_agg2h[2 * N_NODES * F3];    // 2-way split fp16 accum L2
__device__ int     g_is64;

__device__ __forceinline__ void red4h(__half* p, uint32_t a, uint32_t b,
                                      uint32_t c, uint32_t d) {
    asm volatile("red.global.add.noftz.v4.f16x2 [%0], {%1,%2,%3,%4};"
                 :: "l"(p), "r"(a), "r"(b), "r"(c), "r"(d) : "memory");
}

__device__ __forceinline__ float rinv_of(int m) {
    return rsqrtf((float)(g_cnt[m] + 1));
}

__device__ __forceinline__ void mma16816(float* d, const uint32_t* a, const uint32_t* b) {
    asm volatile(
        "mma.sync.aligned.m16n8k16.row.col.f32.f16.f16.f32 "
        "{%0,%1,%2,%3}, {%4,%5,%6,%7}, {%8,%9}, {%0,%1,%2,%3};\n"
        : "+f"(d[0]), "+f"(d[1]), "+f"(d[2]), "+f"(d[3])
        : "r"(a[0]), "r"(a[1]), "r"(a[2]), "r"(a[3]), "r"(b[0]), "r"(b[1]));
}

// ---------------- init: zero histogram + dtype detect ----------------
__global__ void init_kernel(const long long* ei, int M) {
    int i = blockIdx.x * 256 + threadIdx.x;
    if (i < M) g_cnt[i] = 0;
    if (blockIdx.x == 0 && threadIdx.x == 0) {
        bool ok = true;
#pragma unroll
        for (int k = 0; k < 8; k++) {
            long long v = ei[k];
            if (v < 0 || v >= N_NODES) ok = false;
        }
        g_is64 = ok ? 1 : 0;   // int32 data read as int64 lands out of range
    }
}

// ---------------- pack edges to int2 + degree histogram ----------------
__global__ void pack_deg_kernel(const void* ei, int nE) {
    int e = blockIdx.x * 256 + threadIdx.x;
    if (e >= nE) return;
    int s, d;
    if (g_is64) {
        s = (int)((const long long*)ei)[e];
        d = (int)((const long long*)ei)[(long long)nE + e];
    } else {
        s = ((const int*)ei)[e];
        d = ((const int*)ei)[nE + e];
    }
    g_ed[e] = make_int2(s, d);
    atomicAdd(&g_cnt[d], 1);
}

// ---- scale1: zsh = half(z*dinv); agg1 buf0 = self seed, buf1 = 0 ----
__global__ __launch_bounds__(256) void scale1_kernel(const float4* __restrict__ z4, int M) {
    int i = blockIdx.x * 256 + threadIdx.x;     // over M*16 float4
    if (i >= M * 16) return;
    float r = rinv_of(i >> 4);
    float4 v = z4[i];
    __half2 h0 = __floats2half2_rn(v.x * r, v.y * r);
    __half2 h1 = __floats2half2_rn(v.z * r, v.w * r);
    __half2 zz = __floats2half2_rn(0.f, 0.f);
    ((__half2*)g_zsh)[i * 2 + 0] = h0;
    ((__half2*)g_zsh)[i * 2 + 1] = h1;
    ((__half2*)g_agg1h)[i * 2 + 0] = h0;
    ((__half2*)g_agg1h)[i * 2 + 1] = h1;
    ((__half2*)(g_agg1h + N_NODES * F1))[i * 2 + 0] = zz;
    ((__half2*)(g_agg1h + N_NODES * F1))[i * 2 + 1] = zz;
}

// ---- agg: 8 threads/edge, 16B fp16 gather, one red.v4.f16x2, parity-split dst ----
__device__ __forceinline__ void agg_body(const __half* __restrict__ src,
                                         __half* __restrict__ dst, int nE, int stride) {
    int t = blockIdx.x * 256 + threadIdx.x;
    int e = t >> 3;
    if (e >= nE) return;
    int j = t & 7;
    int2 ed = g_ed[e];
    uint4 v = ((const uint4*)src)[ed.x * 8 + j];            // 8 halves
    red4h(dst + (e & 1) * stride + ed.y * 64 + j * 8, v.x, v.y, v.z, v.w);
}

__global__ __launch_bounds__(256) void agg1_kernel(int nE) {
    agg_body(g_zsh, g_agg1h, nE, N_NODES * F1);
}

__global__ __launch_bounds__(256) void agg2_kernel(int nE) {
    agg_body(g_h2h, g_agg2h, nE, N_NODES * F3);
}

// ======== GEMM1 (tensor): xh = relu( ((buf0+buf1)*dinv) @ W1 + b1 ) ========
// block tile 128x128, K=64. A smem stride 72 halves (conflict-free frags).
#define ST1 72
__global__ __launch_bounds__(256) void gemm1_tc(const float* __restrict__ W1,
                                                const float* __restrict__ b1,
                                                int M) {
    __shared__ __half As[128 * ST1];      // 18.4 KB
    __shared__ __half Bs[128 * ST1];      // Bs[n][k] = W1[k][n], 18.4 KB
    int tid  = threadIdx.x;
    int wid  = tid >> 5, lane = tid & 31;
    int g    = lane >> 2, c = lane & 3;
    int m0   = blockIdx.x * 128;

    // B load: W1 [64,128] fp32 row-major -> Bs[n][k] fp16 (transpose)
    const float4* W14 = (const float4*)W1;
#pragma unroll
    for (int i = 0; i < 8; i++) {
        int e4 = tid + 256 * i;           // 0..2047 over 64x32 float4
        int k  = e4 >> 5;
        int n4 = (e4 & 31) * 4;
        float4 w = W14[e4];
        Bs[(n4 + 0) * ST1 + k] = __float2half(w.x);
        Bs[(n4 + 1) * ST1 + k] = __float2half(w.y);
        Bs[(n4 + 2) * ST1 + k] = __float2half(w.z);
        Bs[(n4 + 3) * ST1 + k] = __float2half(w.w);
    }

    // A load: (buf0+buf1)*dinv -> fp16
    const uint4* ag0 = (const uint4*)g_agg1h;
    const uint4* ag1 = (const uint4*)(g_agg1h + N_NODES * F1);
#pragma unroll
    for (int i = 0; i < 4; i++) {
        int e   = tid + 256 * i;          // 0..1023 over 128 rows x 8 uint4
        int rl  = e >> 3, q = e & 7;
        int row = m0 + rl;
        uint4 o = make_uint4(0u, 0u, 0u, 0u);
        if (row < M) {
            uint4 v0 = ag0[row * 8 + q];
            uint4 v1 = ag1[row * 8 + q];
            float r  = rinv_of(row);
            const __half2* p0 = (const __half2*)&v0;
            const __half2* p1 = (const __half2*)&v1;
            __half2* po = (__half2*)&o;
#pragma unroll
            for (int u = 0; u < 4; u++) {
                float2 a = __half22float2(p0[u]);
                float2 b = __half22float2(p1[u]);
                po[u] = __floats2half2_rn((a.x + b.x) * r, (a.y + b.y) * r);
            }
        }
        *(uint4*)&As[rl * ST1 + q * 8] = o;
    }
    __syncthreads();

    int warp_m = wid >> 2, warp_n = wid & 3;   // 2 x 4 warps, warp tile 64x32
    float d[4][4][4];
#pragma unroll
    for (int mt = 0; mt < 4; mt++)
#pragma unroll
        for (int nt = 0; nt < 4; nt++)
#pragma unroll
            for (int u = 0; u < 4; u++) d[mt][nt][u] = 0.f;

#pragma unroll
    for (int ks = 0; ks < 4; ks++) {
        uint32_t a[4][4], bf[4][2];
#pragma unroll
        for (int mt = 0; mt < 4; mt++) {
            int base = (warp_m * 64 + mt * 16 + g) * ST1 + ks * 16 + c * 2;
            a[mt][0] = *(const uint32_t*)&As[base];
            a[mt][1] = *(const uint32_t*)&As[base + 8 * ST1];
            a[mt][2] = *(const uint32_t*)&As[base + 8];
            a[mt][3] = *(const uint32_t*)&As[base + 8 * ST1 + 8];
        }
#pragma unroll
        for (int nt = 0; nt < 4; nt++) {
            int n = warp_n * 32 + nt * 8 + g;
            int kb = ks * 16 + c * 2;
            bf[nt][0] = *(const uint32_t*)&Bs[n * ST1 + kb];
            bf[nt][1] = *(const uint32_t*)&Bs[n * ST1 + kb + 8];
        }
#pragma unroll
        for (int mt = 0; mt < 4; mt++)
#pragma unroll
            for (int nt = 0; nt < 4; nt++)
                mma16816(d[mt][nt], a[mt], bf[nt]);
    }

    // epilogue: x = relu(d + b1), store fp16
    __half2* xh2 = (__half2*)g_xh;
#pragma unroll
    for (int nt = 0; nt < 4; nt++) {
        int n = warp_n * 32 + nt * 8 + c * 2;
        float bx = __ldg(b1 + n), by = __ldg(b1 + n + 1);
#pragma unroll
        for (int mt = 0; mt < 4; mt++) {
            int r0 = m0 + warp_m * 64 + mt * 16 + g;
            if (r0 < M)
                xh2[r0 * 64 + (n >> 1)] = __floats2half2_rn(
                    fmaxf(d[mt][nt][0] + bx, 0.f), fmaxf(d[mt][nt][1] + by, 0.f));
            int r1 = r0 + 8;
            if (r1 < M)
                xh2[r1 * 64 + (n >> 1)] = __floats2half2_rn(
                    fmaxf(d[mt][nt][2] + bx, 0.f), fmaxf(d[mt][nt][3] + by, 0.f));
        }
    }
}

// ======== GEMM2 (tensor, +fused scale2): seeds = half((xh @ W2)*dinv) ========
// block tile 128x64, K=128 in 2 chunks of 64.
__global__ __launch_bounds__(256) void gemm2_tc(const float* __restrict__ W2, int M) {
    __shared__ __half As[128 * ST1];      // chunk: 128 rows x 64 halves
    __shared__ __half Bs[64 * ST1];       // Bs[n][k] chunk
    int tid  = threadIdx.x;
    int wid  = tid >> 5, lane = tid & 31;
    int g    = lane >> 2, c = lane & 3;
    int m0   = blockIdx.x * 128;

    int warp_m = wid >> 1, warp_n = wid & 1;   // 4 x 2 warps, warp tile 32x32
    float d[2][4][4];
#pragma unroll
    for (int mt = 0; mt < 2; mt++)
#pragma unroll
        for (int nt = 0; nt < 4; nt++)
#pragma unroll
            for (int u = 0; u < 4; u++) d[mt][nt][u] = 0.f;

    const uint4*  xh4 = (const uint4*)g_xh;
    const float4* W24 = (const float4*)W2;

    for (int kc = 0; kc < 2; kc++) {
        __syncthreads();
        // A chunk: rows m0..m0+127, k in [kc*64, kc*64+64)
#pragma unroll
        for (int i = 0; i < 4; i++) {
            int e   = tid + 256 * i;      // 0..1023 over 128 x 8 uint4
            int rl  = e >> 3, q = e & 7;
            int row = m0 + rl;
            uint4 v = make_uint4(0u, 0u, 0u, 0u);
            if (row < M) v = xh4[row * 16 + kc * 8 + q];
            *(uint4*)&As[rl * ST1 + q * 8] = v;
        }
        // B chunk: W2 [128,64] fp32 -> Bs[n][k_local]
#pragma unroll
        for (int i = 0; i < 4; i++) {
            int e4 = tid + 256 * i;       // 0..1023 over 64 k x 16 float4
            int kl = e4 >> 4;
            int n4 = (e4 & 15) * 4;
            float4 w = W24[(kc * 64 + kl) * 16 + (e4 & 15)];
            Bs[(n4 + 0) * ST1 + kl] = __float2half(w.x);
            Bs[(n4 + 1) * ST1 + kl] = __float2half(w.y);
            Bs[(n4 + 2) * ST1 + kl] = __float2half(w.z);
            Bs[(n4 + 3) * ST1 + kl] = __float2half(w.w);
        }
        __syncthreads();

#pragma unroll
        for (int ks = 0; ks < 4; ks++) {
            uint32_t a[2][4], bf[4][2];
#pragma unroll
            for (int mt = 0; mt < 2; mt++) {
                int base = (warp_m * 32 + mt * 16 + g) * ST1 + ks * 16 + c * 2;
                a[mt][0] = *(const uint32_t*)&As[base];
                a[mt][1] = *(const uint32_t*)&As[base + 8 * ST1];
                a[mt][2] = *(const uint32_t*)&As[base + 8];
                a[mt][3] = *(const uint32_t*)&As[base + 8 * ST1 + 8];
            }
#pragma unroll
            for (int nt = 0; nt < 4; nt++) {
                int n = warp_n * 32 + nt * 8 + g;
                int kb = ks * 16 + c * 2;
                bf[nt][0] = *(const uint32_t*)&Bs[n * ST1 + kb];
                bf[nt][1] = *(const uint32_t*)&Bs[n * ST1 + kb + 8];
            }
#pragma unroll
            for (int mt = 0; mt < 2; mt++)
#pragma unroll
                for (int nt = 0; nt < 4; nt++)
                    mma16816(d[mt][nt], a[mt], bf[nt]);
        }
    }

    // epilogue: v = d*dinv -> h2h, agg2 buf0 seed; buf1 = 0
    __half2* h2h = (__half2*)g_h2h;
    __half2* s0  = (__half2*)g_agg2h;
    __half2* s1  = (__half2*)(g_agg2h + N_NODES * F3);
    __half2 zz = __floats2half2_rn(0.f, 0.f);
#pragma unroll
    for (int mt = 0; mt < 2; mt++) {
#pragma unroll
        for (int half_row = 0; half_row < 2; half_row++) {
            int row = m0 + warp_m * 32 + mt * 16 + g + half_row * 8;
            if (row >= M) continue;
            float r = rinv_of(row);
#pragma unroll
            for (int nt = 0; nt < 4; nt++) {
                int n = warp_n * 32 + nt * 8 + c * 2;
                float vx = d[mt][nt][half_row * 2 + 0] * r;
                float vy = d[mt][nt][half_row * 2 + 1] * r;
                __half2 h = __floats2half2_rn(vx, vy);
                int idx = row * 32 + (n >> 1);
                h2h[idx] = h;
                s0[idx]  = h;
                s1[idx]  = zz;
            }
        }
    }
}

// ------- epilogue: out = relu((buf0+buf1)*dinv + b2) -------
__global__ __launch_bounds__(256) void epilogue_kernel(const float* __restrict__ b2,
                                                       float* __restrict__ out, int M) {
    int i = blockIdx.x * 256 + threadIdx.x;     // over M*8 uint4-of-halves
    if (i >= M * 8) return;
    int m = i >> 3, c = i & 7;
    float r = rinv_of(m);
    uint4 v0 = ((const uint4*)g_agg2h)[i];
    uint4 v1 = ((const uint4*)(g_agg2h + N_NODES * F3))[i];
    float2 a0 = __half22float2(*(const __half2*)&v0.x);
    float2 a1 = __half22float2(*(const __half2*)&v0.y);
    float2 a2 = __half22float2(*(const __half2*)&v0.z);
    float2 a3 = __half22float2(*(const __half2*)&v0.w);
    float2 c0 = __half22float2(*(const __half2*)&v1.x);
    float2 c1 = __half22float2(*(const __half2*)&v1.y);
    float2 c2 = __half22float2(*(const __half2*)&v1.z);
    float2 c3 = __half22float2(*(const __half2*)&v1.w);
    float4 blo = *(const float4*)(b2 + c * 8);
    float4 bhi = *(const float4*)(b2 + c * 8 + 4);
    float4 o0, o1;
    o0.x = fmaxf((a0.x + c0.x) * r + blo.x, 0.f);
    o0.y = fmaxf((a0.y + c0.y) * r + blo.y, 0.f);
    o0.z = fmaxf((a1.x + c1.x) * r + blo.z, 0.f);
    o0.w = fmaxf((a1.y + c1.y) * r + blo.w, 0.f);
    o1.x = fmaxf((a2.x + c2.x) * r + bhi.x, 0.f);
    o1.y = fmaxf((a2.y + c2.y) * r + bhi.y, 0.f);
    o1.z = fmaxf((a3.x + c3.x) * r + bhi.z, 0.f);
    o1.w = fmaxf((a3.y + c3.y) * r + bhi.w, 0.f);
    ((float4*)out)[i * 2 + 0] = o0;
    ((float4*)out)[i * 2 + 1] = o1;
}

// ---------------- launch ----------------
extern "C" void kernel_launch(void* const* d_in, const int* in_sizes, int n_in,
                              void* d_out, int out_size) {
    const float* z  = (const float*)d_in[0];
    const void*  ei = d_in[1];
    const float* W1 = (const float*)d_in[2];
    const float* b1 = (const float*)d_in[3];
    const float* W2 = (const float*)d_in[4];
    const float* b2 = (const float*)d_in[5];
    float* out = (float*)d_out;

    int nE = in_sizes[1] / 2;
    int M  = in_sizes[0] / F1;

    int nb_nodes = (M + 255) / 256;
    int nb_edge  = (nE + 255) / 256;
    int nb_agg   = (nE * 8 + 255) / 256;
    int nb_vec   = (M * 16 + 255) / 256;
    int nb_epi   = (M * 8 + 255) / 256;
    int nb_tc    = (M + 127) / 128;

    init_kernel<<<nb_nodes, 256>>>((const long long*)ei, M);
    pack_deg_kernel<<<nb_edge, 256>>>(ei, nE);
    scale1_kernel<<<nb_vec, 256>>>((const float4*)z, M);
    agg1_kernel<<<nb_agg, 256>>>(nE);
    gemm1_tc<<<nb_tc, 256>>>(W1, b1, M);
    gemm2_tc<<<nb_tc, 256>>>(W2, M);
    agg2_kernel<<<nb_agg, 256>>>(nE);
    epilogue_kernel<<<nb_epi, 256>>>(b2, out, M);
}

// round 9
// speedup vs baseline: 1.3261x; 1.0946x over previous
#include <cuda_runtime.h>
#include <cuda_fp16.h>
#include <cstdint>

#define N_NODES 50000
#define F1 64
#define F2 128
#define F3 64
#define MAX_E 800000

// ---------------- device scratch ----------------
__device__ int     g_cnt  [N_NODES];             // in-degree; zero at entry, re-zeroed by epilogue
__device__ int2    g_ed   [MAX_E];               // packed {src, dst}
__device__ __half  g_zsh  [N_NODES * F1];        // (z * dinv) fp16 (gather src L1)
__device__ __half  g_agg1h[2 * N_NODES * F1];    // 2-way split fp16 accum L1
__device__ __half  g_h2h  [N_NODES * F3];        // (h2 * dinv) fp16 (gather src L2)
__device__ __half  g_agg2h[2 * N_NODES * F3];    // 2-way split fp16 accum L2

__device__ __forceinline__ void red4h(__half* p, uint32_t a, uint32_t b,
                                      uint32_t c, uint32_t d) {
    asm volatile("red.global.add.noftz.v4.f16x2 [%0], {%1,%2,%3,%4};"
                 :: "l"(p), "r"(a), "r"(b), "r"(c), "r"(d) : "memory");
}

__device__ __forceinline__ float rinv_of(int m) {
    return rsqrtf((float)(g_cnt[m] + 1));
}

__device__ __forceinline__ void mma16816(float* d, const uint32_t* a, const uint32_t* b) {
    asm volatile(
        "mma.sync.aligned.m16n8k16.row.col.f32.f16.f16.f32 "
        "{%0,%1,%2,%3}, {%4,%5,%6,%7}, {%8,%9}, {%0,%1,%2,%3};\n"
        : "+f"(d[0]), "+f"(d[1]), "+f"(d[2]), "+f"(d[3])
        : "r"(a[0]), "r"(a[1]), "r"(a[2]), "r"(a[3]), "r"(b[0]), "r"(b[1]));
}

// ------- pack edges (x2 vectorized) + degree histogram; per-block is64 detect -------
__global__ __launch_bounds__(256) void pack_deg_kernel(const void* ei, int nE) {
    __shared__ int s_is64;
    if (threadIdx.x == 0) {
        const long long* p = (const long long*)ei;
        bool ok = true;
#pragma unroll
        for (int k = 0; k < 8; k++) {
            long long v = p[k];
            if (v < 0 || v >= N_NODES) ok = false;
        }
        s_is64 = ok ? 1 : 0;      // int32 read as int64 lands out of range
    }
    __syncthreads();
    int t = blockIdx.x * 256 + threadIdx.x;      // edges 2t, 2t+1
    if (2 * t >= nE) return;
    int s0, s1, d0, d1;
    if (s_is64) {
        longlong2 sv = ((const longlong2*)ei)[t];
        longlong2 dv = *(const longlong2*)((const long long*)ei + nE + 2 * t);
        s0 = (int)sv.x; s1 = (int)sv.y; d0 = (int)dv.x; d1 = (int)dv.y;
    } else {
        int2 sv = ((const int2*)ei)[t];
        int2 dv = *(const int2*)((const int*)ei + nE + 2 * t);
        s0 = sv.x; s1 = sv.y; d0 = dv.x; d1 = dv.y;
    }
    ((int4*)g_ed)[t] = make_int4(s0, d0, s1, d1);
    atomicAdd(&g_cnt[d0], 1);
    atomicAdd(&g_cnt[d1], 1);
}

// ---- scale1: zsh = half(z*dinv); agg1 buf0 = self seed, buf1 = 0 ----
__global__ __launch_bounds__(256) void scale1_kernel(const float4* __restrict__ z4, int M) {
    int i = blockIdx.x * 256 + threadIdx.x;     // over M*16 float4
    if (i >= M * 16) return;
    float r = rinv_of(i >> 4);
    float4 v = z4[i];
    __half2 h0 = __floats2half2_rn(v.x * r, v.y * r);
    __half2 h1 = __floats2half2_rn(v.z * r, v.w * r);
    __half2 zz = __floats2half2_rn(0.f, 0.f);
    ((__half2*)g_zsh)[i * 2 + 0] = h0;
    ((__half2*)g_zsh)[i * 2 + 1] = h1;
    ((__half2*)g_agg1h)[i * 2 + 0] = h0;
    ((__half2*)g_agg1h)[i * 2 + 1] = h1;
    ((__half2*)(g_agg1h + N_NODES * F1))[i * 2 + 0] = zz;
    ((__half2*)(g_agg1h + N_NODES * F1))[i * 2 + 1] = zz;
}

// ---- agg: 8 threads/edge, 16B fp16 gather, one red.v4.f16x2, parity-split dst ----
__device__ __forceinline__ void agg_body(const __half* __restrict__ src,
                                         __half* __restrict__ dst, int nE, int stride) {
    int t = blockIdx.x * 256 + threadIdx.x;
    int e = t >> 3;
    if (e >= nE) return;
    int j = t & 7;
    int2 ed = g_ed[e];
    uint4 v = ((const uint4*)src)[ed.x * 8 + j];            // 8 halves
    red4h(dst + (e & 1) * stride + ed.y * 64 + j * 8, v.x, v.y, v.z, v.w);
}

__global__ __launch_bounds__(256) void agg1_kernel(int nE) {
    agg_body(g_zsh, g_agg1h, nE, N_NODES * F1);
}

__global__ __launch_bounds__(256) void agg2_kernel(int nE) {
    agg_body(g_h2h, g_agg2h, nE, N_NODES * F3);
}

// ======== Fused GEMM1+GEMM2 (tensor cores) ========
// phase1: x = relu(((buf0+buf1)*dinv) @ W1 + bias1)  -> Xs (smem, fp16)
// phase2: h2 = x @ W2; seeds = half(h2*dinv)
// smem layout (dynamic, halves): As[128*72] | Bs1[128*72]  (Xs[128*136] overlays both)
//                                Bs2[64*136] after them.
#define ST1 72
#define XST 136
#define SMEM_HALVES (2 * 128 * ST1 + 64 * XST)
__global__ __launch_bounds__(256) void gemm_fused(const float* __restrict__ W1,
                                                  const float* __restrict__ bias1,
                                                  const float* __restrict__ W2,
                                                  int M) {
    extern __shared__ __half sh[];
    __half* As  = sh;                    // 128 x 72
    __half* Bs1 = sh + 128 * ST1;        // 128 x 72 (Bs1[n][k] = W1[k][n])
    __half* Xs  = sh;                    // 128 x 136 overlay (phase 2 A)
    __half* Bs2 = sh + 2 * 128 * ST1;    // 64 x 136 (Bs2[n][k] = W2[k][n])

    int tid  = threadIdx.x;
    int wid  = tid >> 5, lane = tid & 31;
    int g    = lane >> 2, c = lane & 3;
    int m0   = blockIdx.x * 128;

    // Bs1: W1 [64,128] fp32 -> Bs1[n][k]
    const float4* W14 = (const float4*)W1;
#pragma unroll
    for (int i = 0; i < 8; i++) {
        int e4 = tid + 256 * i;           // 0..2047 over 64k x 32 float4
        int k  = e4 >> 5;
        int n4 = (e4 & 31) * 4;
        float4 w = W14[e4];
        Bs1[(n4 + 0) * ST1 + k] = __float2half(w.x);
        Bs1[(n4 + 1) * ST1 + k] = __float2half(w.y);
        Bs1[(n4 + 2) * ST1 + k] = __float2half(w.z);
        Bs1[(n4 + 3) * ST1 + k] = __float2half(w.w);
    }
    // Bs2: W2 [128,64] fp32 -> Bs2[n][k]
    const float4* W24 = (const float4*)W2;
#pragma unroll
    for (int i = 0; i < 8; i++) {
        int e4 = tid + 256 * i;           // 0..2047 over 128k x 16 float4
        int k  = e4 >> 4;
        int n4 = (e4 & 15) * 4;
        float4 w = W24[e4];
        Bs2[(n4 + 0) * XST + k] = __float2half(w.x);
        Bs2[(n4 + 1) * XST + k] = __float2half(w.y);
        Bs2[(n4 + 2) * XST + k] = __float2half(w.z);
        Bs2[(n4 + 3) * XST + k] = __float2half(w.w);
    }

    // As: (buf0+buf1)*dinv -> fp16 (rows >= M zeroed)
    const uint4* ag0 = (const uint4*)g_agg1h;
    const uint4* ag1 = (const uint4*)(g_agg1h + N_NODES * F1);
#pragma unroll
    for (int i = 0; i < 4; i++) {
        int e   = tid + 256 * i;          // 0..1023 over 128 rows x 8 uint4
        int rl  = e >> 3, q = e & 7;
        int row = m0 + rl;
        uint4 o = make_uint4(0u, 0u, 0u, 0u);
        if (row < M) {
            uint4 v0 = ag0[row * 8 + q];
            uint4 v1 = ag1[row * 8 + q];
            float r  = rinv_of(row);
            const __half2* p0 = (const __half2*)&v0;
            const __half2* p1 = (const __half2*)&v1;
            __half2* po = (__half2*)&o;
#pragma unroll
            for (int u = 0; u < 4; u++) {
                float2 a = __half22float2(p0[u]);
                float2 b = __half22float2(p1[u]);
                po[u] = __floats2half2_rn((a.x + b.x) * r, (a.y + b.y) * r);
            }
        }
        *(uint4*)&As[rl * ST1 + q * 8] = o;
    }
    __syncthreads();

    // ---- phase 1: 2x4 warps, warp tile 64x32, K=64 ----
    int warp_m = wid >> 2, warp_n = wid & 3;
    float d1[4][4][4];
#pragma unroll
    for (int mt = 0; mt < 4; mt++)
#pragma unroll
        for (int nt = 0; nt < 4; nt++)
#pragma unroll
            for (int u = 0; u < 4; u++) d1[mt][nt][u] = 0.f;

#pragma unroll
    for (int ks = 0; ks < 4; ks++) {
        uint32_t a[4][4], bf[4][2];
#pragma unroll
        for (int mt = 0; mt < 4; mt++) {
            int base = (warp_m * 64 + mt * 16 + g) * ST1 + ks * 16 + c * 2;
            a[mt][0] = *(const uint32_t*)&As[base];
            a[mt][1] = *(const uint32_t*)&As[base + 8 * ST1];
            a[mt][2] = *(const uint32_t*)&As[base + 8];
            a[mt][3] = *(const uint32_t*)&As[base + 8 * ST1 + 8];
        }
#pragma unroll
        for (int nt = 0; nt < 4; nt++) {
            int n = warp_n * 32 + nt * 8 + g;
            int kb = ks * 16 + c * 2;
            bf[nt][0] = *(const uint32_t*)&Bs1[n * ST1 + kb];
            bf[nt][1] = *(const uint32_t*)&Bs1[n * ST1 + kb + 8];
        }
#pragma unroll
        for (int mt = 0; mt < 4; mt++)
#pragma unroll
            for (int nt = 0; nt < 4; nt++)
                mma16816(d1[mt][nt], a[mt], bf[nt]);
    }
    __syncthreads();   // all warps done reading As/Bs1 before Xs overwrite

    // write x = relu(d1 + bias1) into Xs (local rows, fp16)
#pragma unroll
    for (int nt = 0; nt < 4; nt++) {
        int n = warp_n * 32 + nt * 8 + c * 2;
        float bx = __ldg(bias1 + n), by = __ldg(bias1 + n + 1);
#pragma unroll
        for (int mt = 0; mt < 4; mt++) {
            int rl = warp_m * 64 + mt * 16 + g;
            *(__half2*)&Xs[rl * XST + n] = __floats2half2_rn(
                fmaxf(d1[mt][nt][0] + bx, 0.f), fmaxf(d1[mt][nt][1] + by, 0.f));
            *(__half2*)&Xs[(rl + 8) * XST + n] = __floats2half2_rn(
                fmaxf(d1[mt][nt][2] + bx, 0.f), fmaxf(d1[mt][nt][3] + by, 0.f));
        }
    }
    __syncthreads();

    // ---- phase 2: 4x2 warps, warp tile 32x32, K=128 ----
    int wm2 = wid >> 1, wn2 = wid & 1;
    float d2[2][4][4];
#pragma unroll
    for (int mt = 0; mt < 2; mt++)
#pragma unroll
        for (int nt = 0; nt < 4; nt++)
#pragma unroll
            for (int u = 0; u < 4; u++) d2[mt][nt][u] = 0.f;

#pragma unroll
    for (int ks = 0; ks < 8; ks++) {
        uint32_t a[2][4], bf[4][2];
#pragma unroll
        for (int mt = 0; mt < 2; mt++) {
            int base = (wm2 * 32 + mt * 16 + g) * XST + ks * 16 + c * 2;
            a[mt][0] = *(const uint32_t*)&Xs[base];
            a[mt][1] = *(const uint32_t*)&Xs[base + 8 * XST];
            a[mt][2] = *(const uint32_t*)&Xs[base + 8];
            a[mt][3] = *(const uint32_t*)&Xs[base + 8 * XST + 8];
        }
#pragma unroll
        for (int nt = 0; nt < 4; nt++) {
            int n = wn2 * 32 + nt * 8 + g;
            int kb = ks * 16 + c * 2;
            bf[nt][0] = *(const uint32_t*)&Bs2[n * XST + kb];
            bf[nt][1] = *(const uint32_t*)&Bs2[n * XST + kb + 8];
        }
#pragma unroll
        for (int mt = 0; mt < 2; mt++)
#pragma unroll
            for (int nt = 0; nt < 4; nt++)
                mma16816(d2[mt][nt], a[mt], bf[nt]);
    }

    // epilogue: v = d2*dinv -> h2h, agg2 buf0 seed; buf1 = 0
    __half2* h2h = (__half2*)g_h2h;
    __half2* s0  = (__half2*)g_agg2h;
    __half2* s1  = (__half2*)(g_agg2h + N_NODES * F3);
    __half2 zz = __floats2half2_rn(0.f, 0.f);
#pragma unroll
    for (int mt = 0; mt < 2; mt++) {
#pragma unroll
        for (int hr = 0; hr < 2; hr++) {
            int row = m0 + wm2 * 32 + mt * 16 + g + hr * 8;
            if (row >= M) continue;
            float r = rinv_of(row);
#pragma unroll
            for (int nt = 0; nt < 4; nt++) {
                int n = wn2 * 32 + nt * 8 + c * 2;
                __half2 h = __floats2half2_rn(d2[mt][nt][hr * 2 + 0] * r,
                                              d2[mt][nt][hr * 2 + 1] * r);
                int idx = row * 32 + (n >> 1);
                h2h[idx] = h;
                s0[idx]  = h;
                s1[idx]  = zz;
            }
        }
    }
}

// ------- epilogue: out = relu((buf0+buf1)*dinv + b2); then zero g_cnt for next run -------
__global__ __launch_bounds__(256) void epilogue_kernel(const float* __restrict__ b2,
                                                       float* __restrict__ out, int M) {
    int i = blockIdx.x * 256 + threadIdx.x;     // over M*8 uint4-of-halves
    bool act = i < M * 8;
    int m = 0, c = 0;
    float r = 0.f;
    uint4 v0, v1;
    if (act) {
        m = i >> 3; c = i & 7;
        r = rinv_of(m);                          // read g_cnt BEFORE the zeroing below
        v0 = ((const uint4*)g_agg2h)[i];
        v1 = ((const uint4*)(g_agg2h + N_NODES * F3))[i];
    }
    __syncthreads();
    if (!act) return;
    float2 a0 = __half22float2(*(const __half2*)&v0.x);
    float2 a1 = __half22float2(*(const __half2*)&v0.y);
    float2 a2 = __half22float2(*(const __half2*)&v0.z);
    float2 a3 = __half22float2(*(const __half2*)&v0.w);
    float2 c0 = __half22float2(*(const __half2*)&v1.x);
    float2 c1 = __half22float2(*(const __half2*)&v1.y);
    float2 c2 = __half22float2(*(const __half2*)&v1.z);
    float2 c3 = __half22float2(*(const __half2*)&v1.w);
    float4 blo = *(const float4*)(b2 + c * 8);
    float4 bhi = *(const float4*)(b2 + c * 8 + 4);
    float4 o0, o1;
    o0.x = fmaxf((a0.x + c0.x) * r + blo.x, 0.f);
    o0.y = fmaxf((a0.y + c0.y) * r + blo.y, 0.f);
    o0.z = fmaxf((a1.x + c1.x) * r + blo.z, 0.f);
    o0.w = fmaxf((a1.y + c1.y) * r + blo.w, 0.f);
    o1.x = fmaxf((a2.x + c2.x) * r + bhi.x, 0.f);
    o1.y = fmaxf((a2.y + c2.y) * r + bhi.y, 0.f);
    o1.z = fmaxf((a3.x + c3.x) * r + bhi.z, 0.f);
    o1.w = fmaxf((a3.y + c3.y) * r + bhi.w, 0.f);
    ((float4*)out)[i * 2 + 0] = o0;
    ((float4*)out)[i * 2 + 1] = o1;
    if ((i & 7) == 0) g_cnt[m] = 0;              // reset for the next (re)play
}

// ---------------- launch ----------------
extern "C" void kernel_launch(void* const* d_in, const int* in_sizes, int n_in,
                              void* d_out, int out_size) {
    const float* z  = (const float*)d_in[0];
    const void*  ei = d_in[1];
    const float* W1 = (const float*)d_in[2];
    const float* b1 = (const float*)d_in[3];
    const float* W2 = (const float*)d_in[4];
    const float* b2 = (const float*)d_in[5];
    float* out = (float*)d_out;

    int nE = in_sizes[1] / 2;
    int M  = in_sizes[0] / F1;

    int nb_pack = (nE / 2 + 255) / 256;
    int nb_agg  = (nE * 8 + 255) / 256;
    int nb_vec  = (M * 16 + 255) / 256;
    int nb_epi  = (M * 8 + 255) / 256;
    int nb_tc   = (M + 127) / 128;
    int smem_bytes = SMEM_HALVES * 2;            // 54272

    static bool attr_set = false;
    if (!attr_set) {
        cudaFuncSetAttribute(gemm_fused, cudaFuncAttributeMaxDynamicSharedMemorySize,
                             smem_bytes);
        attr_set = true;
    }

    pack_deg_kernel<<<nb_pack, 256>>>(ei, nE);
    scale1_kernel<<<nb_vec, 256>>>((const float4*)z, M);
    agg1_kernel<<<nb_agg, 256>>>(nE);
    gemm_fused<<<nb_tc, 256, smem_bytes>>>(W1, b1, W2, M);
    agg2_kernel<<<nb_agg, 256>>>(nE);
    epilogue_kernel<<<nb_epi, 256>>>(b2, out, M);
}

// round 10
// speedup vs baseline: 1.4629x; 1.1032x over previous
#include <cuda_runtime.h>
#include <cuda_fp16.h>
#include <cstdint>

#define N_NODES 50000
#define F1 64
#define F2 128
#define F3 64
#define MAX_E 800000

// ---------------- device scratch ----------------
__device__ int     g_cnt  [N_NODES];             // in-degree; zero at entry, re-zeroed by epilogue
__device__ int2    g_ed   [MAX_E];               // packed {src, dst}
__device__ __half  g_zsh  [N_NODES * F1];        // (z * dinv) fp16 (gather src L1)
__device__ __half  g_agg1h[2 * N_NODES * F1];    // 2-way split fp16 accum L1
__device__ __half  g_h2h  [N_NODES * F3];        // (h2 * dinv) fp16 (gather src L2)
__device__ __half  g_agg2h[2 * N_NODES * F3];    // 2-way split fp16 accum L2
__device__ __half  g_w1h  [F2 * F1];             // W1^T fp16: [n][k], row stride 64
__device__ __half  g_w2h  [F3 * F2];             // W2^T fp16: [n][k], row stride 128

__device__ __forceinline__ void red4h(__half* p, uint32_t a, uint32_t b,
                                      uint32_t c, uint32_t d) {
    asm volatile("red.global.add.noftz.v4.f16x2 [%0], {%1,%2,%3,%4};"
                 :: "l"(p), "r"(a), "r"(b), "r"(c), "r"(d) : "memory");
}

__device__ __forceinline__ float rinv_of(int m) {
    return rsqrtf((float)(g_cnt[m] + 1));
}

__device__ __forceinline__ void mma16816(float* d, const uint32_t* a, const uint32_t* b) {
    asm volatile(
        "mma.sync.aligned.m16n8k16.row.col.f32.f16.f16.f32 "
        "{%0,%1,%2,%3}, {%4,%5,%6,%7}, {%8,%9}, {%0,%1,%2,%3};\n"
        : "+f"(d[0]), "+f"(d[1]), "+f"(d[2]), "+f"(d[3])
        : "r"(a[0]), "r"(a[1]), "r"(a[2]), "r"(a[3]), "r"(b[0]), "r"(b[1]));
}

// ------- pack edges (x2 vectorized) + degree histogram; per-block is64 detect -------
__global__ __launch_bounds__(256) void pack_deg_kernel(const void* ei, int nE) {
    __shared__ int s_is64;
    if (threadIdx.x == 0) {
        const long long* p = (const long long*)ei;
        bool ok = true;
#pragma unroll
        for (int k = 0; k < 8; k++) {
            long long v = p[k];
            if (v < 0 || v >= N_NODES) ok = false;
        }
        s_is64 = ok ? 1 : 0;      // int32 read as int64 lands out of range
    }
    __syncthreads();
    int t = blockIdx.x * 256 + threadIdx.x;      // edges 2t, 2t+1
    if (2 * t >= nE) return;
    int s0, s1, d0, d1;
    if (s_is64) {
        longlong2 sv = ((const longlong2*)ei)[t];
        longlong2 dv = *(const longlong2*)((const long long*)ei + nE + 2 * t);
        s0 = (int)sv.x; s1 = (int)sv.y; d0 = (int)dv.x; d1 = (int)dv.y;
    } else {
        int2 sv = ((const int2*)ei)[t];
        int2 dv = *(const int2*)((const int*)ei + nE + 2 * t);
        s0 = sv.x; s1 = sv.y; d0 = dv.x; d1 = dv.y;
    }
    ((int4*)g_ed)[t] = make_int4(s0, d0, s1, d1);
    atomicAdd(&g_cnt[d0], 1);
    atomicAdd(&g_cnt[d1], 1);
}

// ---- scale1 (+ fused weight convert): blocks < nbv: zsh/seed; blocks >= nbv: W->fp16^T ----
__global__ __launch_bounds__(256) void scale1_kernel(const float4* __restrict__ z4,
                                                     const float* __restrict__ W1,
                                                     const float* __restrict__ W2,
                                                     int M, int nbv) {
    if ((int)blockIdx.x >= nbv) {
        int j = (blockIdx.x - nbv) * 256 + threadIdx.x;      // 0..4095
#pragma unroll
        for (int u = 0; u < 2; u++) {
            int e = j * 2 + u;
            {   // W1 [64,128]: g_w1h[n*64+k] = W1[k*128+n]
                int k = e >> 7, n = e & 127;
                g_w1h[n * F1 + k] = __float2half(W1[k * F2 + n]);
            }
            {   // W2 [128,64]: g_w2h[n*128+k] = W2[k*64+n]
                int k = e >> 6, n = e & 63;
                g_w2h[n * F2 + k] = __float2half(W2[k * F3 + n]);
            }
        }
        return;
    }
    int i = blockIdx.x * 256 + threadIdx.x;     // over M*16 float4
    if (i >= M * 16) return;
    float r = rinv_of(i >> 4);
    float4 v = z4[i];
    __half2 h0 = __floats2half2_rn(v.x * r, v.y * r);
    __half2 h1 = __floats2half2_rn(v.z * r, v.w * r);
    __half2 zz = __floats2half2_rn(0.f, 0.f);
    ((__half2*)g_zsh)[i * 2 + 0] = h0;
    ((__half2*)g_zsh)[i * 2 + 1] = h1;
    ((__half2*)g_agg1h)[i * 2 + 0] = h0;
    ((__half2*)g_agg1h)[i * 2 + 1] = h1;
    ((__half2*)(g_agg1h + N_NODES * F1))[i * 2 + 0] = zz;
    ((__half2*)(g_agg1h + N_NODES * F1))[i * 2 + 1] = zz;
}

// ---- agg: 8 threads/edge, 16B fp16 gather, one red.v4.f16x2, parity-split dst ----
__device__ __forceinline__ void agg_body(const __half* __restrict__ src,
                                         __half* __restrict__ dst, int nE, int stride) {
    int t = blockIdx.x * 256 + threadIdx.x;
    int e = t >> 3;
    if (e >= nE) return;
    int j = t & 7;
    int2 ed = g_ed[e];
    uint4 v = ((const uint4*)src)[ed.x * 8 + j];            // 8 halves
    red4h(dst + (e & 1) * stride + ed.y * 64 + j * 8, v.x, v.y, v.z, v.w);
}

__global__ __launch_bounds__(256) void agg1_kernel(int nE) {
    agg_body(g_zsh, g_agg1h, nE, N_NODES * F1);
}

__global__ __launch_bounds__(256) void agg2_kernel(int nE) {
    agg_body(g_h2h, g_agg2h, nE, N_NODES * F3);
}

// ======== Fused GEMM1+GEMM2, 64-row tile, pre-converted fp16 weights ========
// smem (halves): As[64*72] | Bs1[128*72]   (Xs[64*136] overlays them)
//                Bs2[64*136] after.
#define ST1 72
#define XST 136
#define SMEM_HALVES (64 * ST1 + 128 * ST1 + 64 * XST)
__global__ __launch_bounds__(256) void gemm_fused(const float* __restrict__ bias1, int M) {
    extern __shared__ __half sh[];
    __half* As  = sh;                    // 64 x 72
    __half* Bs1 = sh + 64 * ST1;         // 128 x 72
    __half* Xs  = sh;                    // 64 x 136 overlay
    __half* Bs2 = sh + 64 * ST1 + 128 * ST1;   // 64 x 136

    int tid  = threadIdx.x;
    int wid  = tid >> 5, lane = tid & 31;
    int g    = lane >> 2, c = lane & 3;
    int m0   = blockIdx.x * 64;

    // Bs1: 128 rows x 8 uint4 (vectorized, conflict-free)
    const uint4* w1v = (const uint4*)g_w1h;
#pragma unroll
    for (int i = 0; i < 4; i++) {
        int e = tid + 256 * i;            // 0..1023
        int n = e >> 3, q = e & 7;
        *(uint4*)&Bs1[n * ST1 + q * 8] = w1v[e];
    }
    // Bs2: 64 rows x 16 uint4
    const uint4* w2v = (const uint4*)g_w2h;
#pragma unroll
    for (int i = 0; i < 4; i++) {
        int e = tid + 256 * i;            // 0..1023
        int n = e >> 4, q = e & 15;
        *(uint4*)&Bs2[n * XST + q * 8] = w2v[e];
    }
    // As: (buf0+buf1)*dinv -> fp16 (64 rows x 8 uint4)
    const uint4* ag0 = (const uint4*)g_agg1h;
    const uint4* ag1 = (const uint4*)(g_agg1h + N_NODES * F1);
#pragma unroll
    for (int i = 0; i < 2; i++) {
        int e   = tid + 256 * i;          // 0..511
        int rl  = e >> 3, q = e & 7;
        int row = m0 + rl;
        uint4 o = make_uint4(0u, 0u, 0u, 0u);
        if (row < M) {
            uint4 v0 = ag0[row * 8 + q];
            uint4 v1 = ag1[row * 8 + q];
            float r  = rinv_of(row);
            const __half2* p0 = (const __half2*)&v0;
            const __half2* p1 = (const __half2*)&v1;
            __half2* po = (__half2*)&o;
#pragma unroll
            for (int u = 0; u < 4; u++) {
                float2 a = __half22float2(p0[u]);
                float2 b = __half22float2(p1[u]);
                po[u] = __floats2half2_rn((a.x + b.x) * r, (a.y + b.y) * r);
            }
        }
        *(uint4*)&As[rl * ST1 + q * 8] = o;
    }
    __syncthreads();

    // ---- phase 1: 2x4 warps, warp tile 32x32, K=64 ----
    int warp_m = wid >> 2, warp_n = wid & 3;
    float d1[2][4][4];
#pragma unroll
    for (int mt = 0; mt < 2; mt++)
#pragma unroll
        for (int nt = 0; nt < 4; nt++)
#pragma unroll
            for (int u = 0; u < 4; u++) d1[mt][nt][u] = 0.f;

#pragma unroll
    for (int ks = 0; ks < 4; ks++) {
        uint32_t a[2][4], bf[4][2];
#pragma unroll
        for (int mt = 0; mt < 2; mt++) {
            int base = (warp_m * 32 + mt * 16 + g) * ST1 + ks * 16 + c * 2;
            a[mt][0] = *(const uint32_t*)&As[base];
            a[mt][1] = *(const uint32_t*)&As[base + 8 * ST1];
            a[mt][2] = *(const uint32_t*)&As[base + 8];
            a[mt][3] = *(const uint32_t*)&As[base + 8 * ST1 + 8];
        }
#pragma unroll
        for (int nt = 0; nt < 4; nt++) {
            int n = warp_n * 32 + nt * 8 + g;
            int kb = ks * 16 + c * 2;
            bf[nt][0] = *(const uint32_t*)&Bs1[n * ST1 + kb];
            bf[nt][1] = *(const uint32_t*)&Bs1[n * ST1 + kb + 8];
        }
#pragma unroll
        for (int mt = 0; mt < 2; mt++)
#pragma unroll
            for (int nt = 0; nt < 4; nt++)
                mma16816(d1[mt][nt], a[mt], bf[nt]);
    }
    __syncthreads();   // done reading As/Bs1 before Xs overwrite

    // write x = relu(d1 + bias1) into Xs
#pragma unroll
    for (int nt = 0; nt < 4; nt++) {
        int n = warp_n * 32 + nt * 8 + c * 2;
        float bx = __ldg(bias1 + n), by = __ldg(bias1 + n + 1);
#pragma unroll
        for (int mt = 0; mt < 2; mt++) {
            int rl = warp_m * 32 + mt * 16 + g;
            *(__half2*)&Xs[rl * XST + n] = __floats2half2_rn(
                fmaxf(d1[mt][nt][0] + bx, 0.f), fmaxf(d1[mt][nt][1] + by, 0.f));
            *(__half2*)&Xs[(rl + 8) * XST + n] = __floats2half2_rn(
                fmaxf(d1[mt][nt][2] + bx, 0.f), fmaxf(d1[mt][nt][3] + by, 0.f));
        }
    }
    __syncthreads();

    // ---- phase 2: 4x2 warps, warp tile 16x32, K=128 ----
    int wm2 = wid >> 1, wn2 = wid & 1;
    float d2[4][4];
#pragma unroll
    for (int nt = 0; nt < 4; nt++)
#pragma unroll
        for (int u = 0; u < 4; u++) d2[nt][u] = 0.f;

#pragma unroll
    for (int ks = 0; ks < 8; ks++) {
        uint32_t a[4], bf[4][2];
        int base = (wm2 * 16 + g) * XST + ks * 16 + c * 2;
        a[0] = *(const uint32_t*)&Xs[base];
        a[1] = *(const uint32_t*)&Xs[base + 8 * XST];
        a[2] = *(const uint32_t*)&Xs[base + 8];
        a[3] = *(const uint32_t*)&Xs[base + 8 * XST + 8];
#pragma unroll
        for (int nt = 0; nt < 4; nt++) {
            int n = wn2 * 32 + nt * 8 + g;
            int kb = ks * 16 + c * 2;
            bf[nt][0] = *(const uint32_t*)&Bs2[n * XST + kb];
            bf[nt][1] = *(const uint32_t*)&Bs2[n * XST + kb + 8];
        }
#pragma unroll
        for (int nt = 0; nt < 4; nt++)
            mma16816(d2[nt], a, bf[nt]);
    }

    // epilogue: v = d2*dinv -> h2h, agg2 buf0 seed; buf1 = 0
    __half2* h2h = (__half2*)g_h2h;
    __half2* s0  = (__half2*)g_agg2h;
    __half2* s1  = (__half2*)(g_agg2h + N_NODES * F3);
    __half2 zz = __floats2half2_rn(0.f, 0.f);
#pragma unroll
    for (int hr = 0; hr < 2; hr++) {
        int row = m0 + wm2 * 16 + g + hr * 8;
        if (row >= M) continue;
        float r = rinv_of(row);
#pragma unroll
        for (int nt = 0; nt < 4; nt++) {
            int n = wn2 * 32 + nt * 8 + c * 2;
            __half2 h = __floats2half2_rn(d2[nt][hr * 2 + 0] * r,
                                          d2[nt][hr * 2 + 1] * r);
            int idx = row * 32 + (n >> 1);
            h2h[idx] = h;
            s0[idx]  = h;
            s1[idx]  = zz;
        }
    }
}

// ------- epilogue: out = relu((buf0+buf1)*dinv + b2); then zero g_cnt for next run -------
__global__ __launch_bounds__(256) void epilogue_kernel(const float* __restrict__ b2,
                                                       float* __restrict__ out, int M) {
    int i = blockIdx.x * 256 + threadIdx.x;     // over M*8 uint4-of-halves
    bool act = i < M * 8;
    int m = 0, c = 0;
    float r = 0.f;
    uint4 v0, v1;
    if (act) {
        m = i >> 3; c = i & 7;
        r = rinv_of(m);                          // read g_cnt BEFORE zeroing
        v0 = ((const uint4*)g_agg2h)[i];
        v1 = ((const uint4*)(g_agg2h + N_NODES * F3))[i];
    }
    __syncthreads();
    if (!act) return;
    float2 a0 = __half22float2(*(const __half2*)&v0.x);
    float2 a1 = __half22float2(*(const __half2*)&v0.y);
    float2 a2 = __half22float2(*(const __half2*)&v0.z);
    float2 a3 = __half22float2(*(const __half2*)&v0.w);
    float2 c0 = __half22float2(*(const __half2*)&v1.x);
    float2 c1 = __half22float2(*(const __half2*)&v1.y);
    float2 c2 = __half22float2(*(const __half2*)&v1.z);
    float2 c3 = __half22float2(*(const __half2*)&v1.w);
    float4 blo = *(const float4*)(b2 + c * 8);
    float4 bhi = *(const float4*)(b2 + c * 8 + 4);
    float4 o0, o1;
    o0.x = fmaxf((a0.x + c0.x) * r + blo.x, 0.f);
    o0.y = fmaxf((a0.y + c0.y) * r + blo.y, 0.f);
    o0.z = fmaxf((a1.x + c1.x) * r + blo.z, 0.f);
    o0.w = fmaxf((a1.y + c1.y) * r + blo.w, 0.f);
    o1.x = fmaxf((a2.x + c2.x) * r + bhi.x, 0.f);
    o1.y = fmaxf((a2.y + c2.y) * r + bhi.y, 0.f);
    o1.z = fmaxf((a3.x + c3.x) * r + bhi.z, 0.f);
    o1.w = fmaxf((a3.y + c3.y) * r + bhi.w, 0.f);
    ((float4*)out)[i * 2 + 0] = o0;
    ((float4*)out)[i * 2 + 1] = o1;
    if ((i & 7) == 0) g_cnt[m] = 0;              // reset for next (re)play
}

// ---------------- launch ----------------
extern "C" void kernel_launch(void* const* d_in, const int* in_sizes, int n_in,
                              void* d_out, int out_size) {
    const float* z  = (const float*)d_in[0];
    const void*  ei = d_in[1];
    const float* W1 = (const float*)d_in[2];
    const float* b1 = (const float*)d_in[3];
    const float* W2 = (const float*)d_in[4];
    const float* b2 = (const float*)d_in[5];
    float* out = (float*)d_out;

    int nE = in_sizes[1] / 2;
    int M  = in_sizes[0] / F1;

    int nb_pack = (nE / 2 + 255) / 256;
    int nb_agg  = (nE * 8 + 255) / 256;
    int nb_vec  = (M * 16 + 255) / 256;
    int nb_epi  = (M * 8 + 255) / 256;
    int nb_tc   = (M + 63) / 64;
    int smem_bytes = SMEM_HALVES * 2;            // 45056

    static bool attr_set = false;
    if (!attr_set) {
        cudaFuncSetAttribute(gemm_fused, cudaFuncAttributeMaxDynamicSharedMemorySize,
                             smem_bytes);
        attr_set = true;
    }

    pack_deg_kernel<<<nb_pack, 256>>>(ei, nE);
    scale1_kernel<<<nb_vec + 16, 256>>>((const float4*)z, W1, W2, M, nb_vec);
    agg1_kernel<<<nb_agg, 256>>>(nE);
    gemm_fused<<<nb_tc, 256, smem_bytes>>>(b1, M);
    agg2_kernel<<<nb_agg, 256>>>(nE);
    epilogue_kernel<<<nb_epi, 256>>>(b2, out, M);
}